// round 1
// baseline (speedup 1.0000x reference)
#include <cuda_runtime.h>
#include <math.h>
#include <stdint.h>

// ---------------------------------------------------------------------------
// SpatialHead: coordconv(256+2->64)+BN+ReLU -> offsetconv(64->18) ->
// deformconv(64->64)+BN+ReLU -> 2x [conv3x3(64->64)+BN+ReLU] -> 1x1 conv -> sigmoid
// B=8, H=W=96. All activations NHWC (channels contiguous).
// ---------------------------------------------------------------------------

namespace sh {
constexpr int kB = 8, kH = 96, kW = 96;
constexpr int kPos = kB * kH * kW;          // 73728
constexpr float kEps = 1e-5f;
}

// ------------------------- scratch (__device__ globals) --------------------
__device__ __align__(16) float g_buf0[sh::kPos * 64];          // x1 / x3
__device__ __align__(16) float g_buf1[sh::kPos * 64];          // x2 / x4
__device__ __align__(16) float g_offb[sh::kPos * 18];          // offsets NHWC
__device__ __align__(16) float g_samp[(size_t)sh::kPos * 576]; // bilinear samples [pos][tap][c]
__device__ __align__(16) float g_w1t[2304 * 64];               // coord conv weights [k=t*256+c][o]
__device__ __align__(16) float g_cb[sh::kH * sh::kW * 64];     // coord-channel contribution + bias
__device__ __align__(16) float g_wofft[576 * 32];              // offset conv weights, padded to 32 out
__device__ __align__(16) float g_wdct[576 * 64];               // deform einsum weights [t*64+c][o]
__device__ __align__(16) float g_wr1t[576 * 64];
__device__ __align__(16) float g_wr2t[576 * 64];
__device__ float g_bnsc[4 * 64];
__device__ float g_bnsh[4 * 64];

// ------------------------------ prep kernel --------------------------------
// Repacks all weights to [k][o] layout, precomputes the coord-channel bias map
// and folded BN scale/shift. Runs every call (cheap, deterministic).
__global__ void prep_kernel(
    const float* __restrict__ coord_w, const float* __restrict__ coord_b,
    const float* __restrict__ off_w, const float* __restrict__ dc_w,
    const float* __restrict__ r1_w, const float* __restrict__ r2_w,
    const float* __restrict__ bn1g, const float* __restrict__ bn1b,
    const float* __restrict__ bn1m, const float* __restrict__ bn1v,
    const float* __restrict__ bn2g, const float* __restrict__ bn2b,
    const float* __restrict__ bn2m, const float* __restrict__ bn2v,
    const float* __restrict__ bn3g, const float* __restrict__ bn3b,
    const float* __restrict__ bn3m, const float* __restrict__ bn3v,
    const float* __restrict__ bn4g, const float* __restrict__ bn4b,
    const float* __restrict__ bn4m, const float* __restrict__ bn4v)
{
    int idx = blockIdx.x * blockDim.x + threadIdx.x;
    const int N1 = 2304 * 64;           // g_w1t
    const int N2 = sh::kH * sh::kW * 64; // g_cb
    const int N3 = 576 * 32;            // g_wofft
    const int N4 = 576 * 64;            // g_wdct / g_wr1t / g_wr2t

    if (idx < N1) {
        int o = idx & 63, k = idx >> 6;
        int t = k >> 8, c = k & 255;
        g_w1t[idx] = coord_w[(o * 258 + c) * 9 + t];
        return;
    }
    idx -= N1;
    if (idx < N2) {
        int o = idx & 63, p = idx >> 6;
        int y = p / 96, x = p % 96;
        float acc = coord_b[o];
        #pragma unroll
        for (int t = 0; t < 9; t++) {
            int yy = y + t / 3 - 1, xx = x + t % 3 - 1;
            if ((unsigned)yy < 96u && (unsigned)xx < 96u) {
                float xv = fmaf((float)xx, 2.0f / 95.0f, -1.0f);
                float yv = fmaf((float)yy, 2.0f / 95.0f, -1.0f);
                acc = fmaf(coord_w[(o * 258 + 256) * 9 + t], xv, acc);
                acc = fmaf(coord_w[(o * 258 + 257) * 9 + t], yv, acc);
            }
        }
        g_cb[p * 64 + o] = acc;
        return;
    }
    idx -= N2;
    if (idx < N3) {
        int o = idx & 31, k = idx >> 5;
        int t = k >> 6, c = k & 63;
        g_wofft[idx] = (o < 18) ? off_w[(o * 64 + c) * 9 + t] : 0.0f;
        return;
    }
    idx -= N3;
    if (idx < N4) {
        int o = idx & 63, k = idx >> 6;
        int t = k >> 6, c = k & 63;
        g_wdct[idx] = dc_w[(o * 64 + c) * 9 + t];
        return;
    }
    idx -= N4;
    if (idx < N4) {
        int o = idx & 63, k = idx >> 6;
        int t = k >> 6, c = k & 63;
        g_wr1t[idx] = r1_w[(o * 64 + c) * 9 + t];
        return;
    }
    idx -= N4;
    if (idx < N4) {
        int o = idx & 63, k = idx >> 6;
        int t = k >> 6, c = k & 63;
        g_wr2t[idx] = r2_w[(o * 64 + c) * 9 + t];
        return;
    }
    idx -= N4;
    if (idx < 512) {
        int which = idx >> 7, r = idx & 127, o = r & 63;
        const float* gs; const float* bs; const float* ms; const float* vs;
        if (which == 0)      { gs = bn1g; bs = bn1b; ms = bn1m; vs = bn1v; }
        else if (which == 1) { gs = bn2g; bs = bn2b; ms = bn2m; vs = bn2v; }
        else if (which == 2) { gs = bn3g; bs = bn3b; ms = bn3m; vs = bn3v; }
        else                 { gs = bn4g; bs = bn4b; ms = bn4m; vs = bn4v; }
        float sc = gs[o] * rsqrtf(vs[o] + sh::kEps);
        if (r < 64) g_bnsc[which * 64 + o] = sc;
        else        g_bnsh[which * 64 + o] = bs[o] - ms[o] * sc;
    }
}

// ------------------------------ conv GEMM ----------------------------------
// Implicit-GEMM 3x3 (or 1x1 for TAPS==1) conv over NHWC input.
// Block: 32 positions (one x-strip of a row) x BN output channels.
// Threads = 2*BN. Micro-tile 4 pos x 4 ch. K-chunks of 32 stay inside one tap.
// MODE 0: + per-position bias (coord) + BN + ReLU  (conv1)
// MODE 1: + channel bias, store first 18 channels   (offset conv)
// MODE 2: + BN + ReLU                               (deform / r1 / r2)
template <int CIN, int TAPS, int BN, int MODE>
__global__ void __launch_bounds__(2 * BN)
conv_gemm(const float* __restrict__ in, const float* __restrict__ wT,
          const float* __restrict__ posbias, const float* __restrict__ chbias,
          const float* __restrict__ bnsc, const float* __restrict__ bnsh,
          float* __restrict__ out)
{
    constexpr int CPT = CIN / 32;       // chunks per tap
    constexpr int KCH = TAPS * CPT;
    __shared__ float sA[32][36];        // [c][pos] transposed, padded
    __shared__ float sB[32][BN];        // [c][o]

    const int tid = threadIdx.x;
    const int x0 = blockIdx.x * 32;
    const int y = blockIdx.y;
    const int b = blockIdx.z;
    const int pos0 = (b * sh::kH + y) * sh::kW + x0;

    float acc[4][4];
    #pragma unroll
    for (int i = 0; i < 4; i++)
        #pragma unroll
        for (int j = 0; j < 4; j++) acc[i][j] = 0.0f;

    const int pg = tid & 7;     // position group (x4)
    const int cg = tid >> 3;    // channel group (x4)

    for (int ch = 0; ch < KCH; ch++) {
        const int t = ch / CPT;
        const int c0 = (ch % CPT) * 32;
        const int dy = (TAPS == 1) ? 0 : (t / 3 - 1);
        const int dx = (TAPS == 1) ? 0 : (t % 3 - 1);

        if constexpr (BN == 64) {   // 128 threads
            // A tile: 32 pos x 32 c, 8 floats/thread
            {
                const int i = tid >> 2;
                const int cb4 = (tid & 3) * 8;
                const int yy = y + dy, xx = x0 + i + dx;
                float4 v0 = make_float4(0.f, 0.f, 0.f, 0.f), v1 = v0;
                if (TAPS == 1 || ((unsigned)yy < (unsigned)sh::kH &&
                                  (unsigned)xx < (unsigned)sh::kW)) {
                    const float* src = in + (size_t)((b * sh::kH + yy) * sh::kW + xx) * CIN + c0 + cb4;
                    v0 = *(const float4*)src;
                    v1 = *(const float4*)(src + 4);
                }
                sA[cb4 + 0][i] = v0.x; sA[cb4 + 1][i] = v0.y;
                sA[cb4 + 2][i] = v0.z; sA[cb4 + 3][i] = v0.w;
                sA[cb4 + 4][i] = v1.x; sA[cb4 + 5][i] = v1.y;
                sA[cb4 + 6][i] = v1.z; sA[cb4 + 7][i] = v1.w;
            }
            // B tile: 32 x 64, 16 floats/thread
            {
                const int r = tid >> 2;
                const int cc = (tid & 3) * 16;
                const float* ws = wT + (size_t)(ch * 32 + r) * BN + cc;
                float4* dst = (float4*)&sB[r][cc];
                dst[0] = ((const float4*)ws)[0];
                dst[1] = ((const float4*)ws)[1];
                dst[2] = ((const float4*)ws)[2];
                dst[3] = ((const float4*)ws)[3];
            }
        } else {                    // BN == 32, 64 threads
            {
                const int i = tid >> 1;
                const int cb4 = (tid & 1) * 16;
                const int yy = y + dy, xx = x0 + i + dx;
                float4 v[4];
                if (TAPS == 1 || ((unsigned)yy < (unsigned)sh::kH &&
                                  (unsigned)xx < (unsigned)sh::kW)) {
                    const float* src = in + (size_t)((b * sh::kH + yy) * sh::kW + xx) * CIN + c0 + cb4;
                    v[0] = ((const float4*)src)[0]; v[1] = ((const float4*)src)[1];
                    v[2] = ((const float4*)src)[2]; v[3] = ((const float4*)src)[3];
                } else {
                    v[0] = v[1] = v[2] = v[3] = make_float4(0.f, 0.f, 0.f, 0.f);
                }
                #pragma unroll
                for (int q = 0; q < 4; q++) {
                    sA[cb4 + q * 4 + 0][i] = v[q].x;
                    sA[cb4 + q * 4 + 1][i] = v[q].y;
                    sA[cb4 + q * 4 + 2][i] = v[q].z;
                    sA[cb4 + q * 4 + 3][i] = v[q].w;
                }
            }
            {
                const int r = tid >> 1;
                const int cc = (tid & 1) * 16;
                const float* ws = wT + (size_t)(ch * 32 + r) * BN + cc;
                float4* dst = (float4*)&sB[r][cc];
                #pragma unroll
                for (int q = 0; q < 4; q++) dst[q] = ((const float4*)ws)[q];
            }
        }
        __syncthreads();

        #pragma unroll
        for (int k = 0; k < 32; k++) {
            float4 av = *(const float4*)&sA[k][pg * 4];
            float4 bv = *(const float4*)&sB[k][cg * 4];
            acc[0][0] = fmaf(av.x, bv.x, acc[0][0]);
            acc[0][1] = fmaf(av.x, bv.y, acc[0][1]);
            acc[0][2] = fmaf(av.x, bv.z, acc[0][2]);
            acc[0][3] = fmaf(av.x, bv.w, acc[0][3]);
            acc[1][0] = fmaf(av.y, bv.x, acc[1][0]);
            acc[1][1] = fmaf(av.y, bv.y, acc[1][1]);
            acc[1][2] = fmaf(av.y, bv.z, acc[1][2]);
            acc[1][3] = fmaf(av.y, bv.w, acc[1][3]);
            acc[2][0] = fmaf(av.z, bv.x, acc[2][0]);
            acc[2][1] = fmaf(av.z, bv.y, acc[2][1]);
            acc[2][2] = fmaf(av.z, bv.z, acc[2][2]);
            acc[2][3] = fmaf(av.z, bv.w, acc[2][3]);
            acc[3][0] = fmaf(av.w, bv.x, acc[3][0]);
            acc[3][1] = fmaf(av.w, bv.y, acc[3][1]);
            acc[3][2] = fmaf(av.w, bv.z, acc[3][2]);
            acc[3][3] = fmaf(av.w, bv.w, acc[3][3]);
        }
        __syncthreads();
    }

    // epilogue
    #pragma unroll
    for (int ii = 0; ii < 4; ii++) {
        const int p = pg * 4 + ii;
        const int pos = pos0 + p;
        #pragma unroll
        for (int jj = 0; jj < 4; jj++) {
            const int o = cg * 4 + jj;
            float v = acc[ii][jj];
            if constexpr (MODE == 0) {
                v += posbias[(size_t)((y * sh::kW) + x0 + p) * 64 + o];
                v = fmaf(v, bnsc[o], bnsh[o]);
                v = fmaxf(v, 0.0f);
                out[(size_t)pos * 64 + o] = v;
            } else if constexpr (MODE == 1) {
                v += chbias[o];
                if (o < 18) out[(size_t)pos * 18 + o] = v;
            } else {
                v = fmaf(v, bnsc[o], bnsh[o]);
                v = fmaxf(v, 0.0f);
                out[(size_t)pos * 64 + o] = v;
            }
        }
    }
}

// --------------------------- deform sampling -------------------------------
__device__ __forceinline__ void corner_acc(const float4* __restrict__ base,
                                           int yy, int xx, int cq, float w,
                                           float4& acc)
{
    if ((unsigned)yy < 96u && (unsigned)xx < 96u) {
        float4 v = base[(yy * 96 + xx) * 16 + cq];
        acc.x = fmaf(w, v.x, acc.x);
        acc.y = fmaf(w, v.y, acc.y);
        acc.z = fmaf(w, v.z, acc.z);
        acc.w = fmaf(w, v.w, acc.w);
    }
}

__global__ void sample_kernel(const float* __restrict__ x1,
                              const float* __restrict__ offs,
                              float* __restrict__ samp)
{
    int gid = blockIdx.x * blockDim.x + threadIdx.x;   // kPos * 16
    if (gid >= sh::kPos * 16) return;
    const int cq = gid & 15;
    const int pos = gid >> 4;
    const int b = pos / (sh::kH * sh::kW);
    const int rem = pos % (sh::kH * sh::kW);
    const int y = rem / sh::kW, x = rem % sh::kW;

    const float* op = offs + (size_t)pos * 18;
    const float4* base = (const float4*)x1 + (size_t)(b * sh::kH * sh::kW) * 16;
    float4* outp = (float4*)(samp + (size_t)pos * 576);

    #pragma unroll
    for (int t = 0; t < 9; t++) {
        float oy = op[2 * t];
        float ox = op[2 * t + 1];
        float py = (float)(y + t / 3 - 1) + oy;
        float px = (float)(x + t % 3 - 1) + ox;
        float y0f = floorf(py), x0f = floorf(px);
        float fy = py - y0f, fx = px - x0f;
        int y0 = (int)y0f, xx0 = (int)x0f;
        float w00 = (1.0f - fy) * (1.0f - fx);
        float w01 = (1.0f - fy) * fx;
        float w10 = fy * (1.0f - fx);
        float w11 = fy * fx;
        float4 acc = make_float4(0.f, 0.f, 0.f, 0.f);
        corner_acc(base, y0,     xx0,     cq, w00, acc);
        corner_acc(base, y0,     xx0 + 1, cq, w01, acc);
        corner_acc(base, y0 + 1, xx0,     cq, w10, acc);
        corner_acc(base, y0 + 1, xx0 + 1, cq, w11, acc);
        outp[t * 16 + cq] = acc;
    }
}

// ------------------------------ final 1x1 ----------------------------------
__global__ void final_kernel(const float* __restrict__ x4,
                             const float* __restrict__ ow,
                             const float* __restrict__ ob,
                             float* __restrict__ out)
{
    int pos = blockIdx.x * blockDim.x + threadIdx.x;
    if (pos >= sh::kPos) return;
    const float4* xr = (const float4*)(x4 + (size_t)pos * 64);
    const float4* wr = (const float4*)ow;
    float acc = ob[0];
    #pragma unroll
    for (int q = 0; q < 16; q++) {
        float4 a = xr[q], w = wr[q];
        acc = fmaf(a.x, w.x, acc);
        acc = fmaf(a.y, w.y, acc);
        acc = fmaf(a.z, w.z, acc);
        acc = fmaf(a.w, w.w, acc);
    }
    out[pos] = 1.0f / (1.0f + expf(-acc));
}

// ------------------------------ launcher -----------------------------------
extern "C" void kernel_launch(void* const* d_in, const int* in_sizes, int n_in,
                              void* d_out, int out_size)
{
    const float* features = (const float*)d_in[0];
    const float* coord_w  = (const float*)d_in[1];
    const float* coord_b  = (const float*)d_in[2];
    const float* bn1g = (const float*)d_in[3];
    const float* bn1b = (const float*)d_in[4];
    const float* bn1m = (const float*)d_in[5];
    const float* bn1v = (const float*)d_in[6];
    const float* off_w = (const float*)d_in[7];
    const float* off_b = (const float*)d_in[8];
    const float* dc_w  = (const float*)d_in[9];
    const float* bn2g = (const float*)d_in[10];
    const float* bn2b = (const float*)d_in[11];
    const float* bn2m = (const float*)d_in[12];
    const float* bn2v = (const float*)d_in[13];
    const float* r1_w = (const float*)d_in[14];
    const float* bn3g = (const float*)d_in[15];
    const float* bn3b = (const float*)d_in[16];
    const float* bn3m = (const float*)d_in[17];
    const float* bn3v = (const float*)d_in[18];
    const float* r2_w = (const float*)d_in[19];
    const float* bn4g = (const float*)d_in[20];
    const float* bn4b = (const float*)d_in[21];
    const float* bn4m = (const float*)d_in[22];
    const float* bn4v = (const float*)d_in[23];
    const float* out_w = (const float*)d_in[24];
    const float* out_b = (const float*)d_in[25];

    float *p_buf0, *p_buf1, *p_off, *p_samp, *p_w1t, *p_cb, *p_wofft,
          *p_wdct, *p_wr1t, *p_wr2t, *p_bnsc, *p_bnsh;
    cudaGetSymbolAddress((void**)&p_buf0, g_buf0);
    cudaGetSymbolAddress((void**)&p_buf1, g_buf1);
    cudaGetSymbolAddress((void**)&p_off,  g_offb);
    cudaGetSymbolAddress((void**)&p_samp, g_samp);
    cudaGetSymbolAddress((void**)&p_w1t,  g_w1t);
    cudaGetSymbolAddress((void**)&p_cb,   g_cb);
    cudaGetSymbolAddress((void**)&p_wofft, g_wofft);
    cudaGetSymbolAddress((void**)&p_wdct, g_wdct);
    cudaGetSymbolAddress((void**)&p_wr1t, g_wr1t);
    cudaGetSymbolAddress((void**)&p_wr2t, g_wr2t);
    cudaGetSymbolAddress((void**)&p_bnsc, g_bnsc);
    cudaGetSymbolAddress((void**)&p_bnsh, g_bnsh);

    // 1. prep: repack weights, coord bias map, folded BN params
    const int prep_total = 2304 * 64 + 96 * 96 * 64 + 576 * 32 + 3 * 576 * 64 + 512;
    prep_kernel<<<(prep_total + 255) / 256, 256>>>(
        coord_w, coord_b, off_w, dc_w, r1_w, r2_w,
        bn1g, bn1b, bn1m, bn1v, bn2g, bn2b, bn2m, bn2v,
        bn3g, bn3b, bn3m, bn3v, bn4g, bn4b, bn4m, bn4v);

    dim3 grid(3, 96, 8);

    // 2. coord conv (256->64) + coord bias + BN1 + ReLU -> buf0
    conv_gemm<256, 9, 64, 0><<<grid, 128>>>(
        features, p_w1t, p_cb, nullptr, p_bnsc + 0, p_bnsh + 0, p_buf0);

    // 3. offset conv (64->18) + bias -> g_offb
    conv_gemm<64, 9, 32, 1><<<grid, 64>>>(
        p_buf0, p_wofft, nullptr, off_b, nullptr, nullptr, p_off);

    // 4. deform bilinear sampling -> g_samp [pos][tap][c]
    sample_kernel<<<(sh::kPos * 16 + 255) / 256, 256>>>(p_buf0, p_off, p_samp);

    // 5. deform einsum (GEMM over K=576) + BN2 + ReLU -> buf1
    conv_gemm<576, 1, 64, 2><<<grid, 128>>>(
        p_samp, p_wdct, nullptr, nullptr, p_bnsc + 64, p_bnsh + 64, p_buf1);

    // 6. r1 conv + BN3 + ReLU -> buf0
    conv_gemm<64, 9, 64, 2><<<grid, 128>>>(
        p_buf1, p_wr1t, nullptr, nullptr, p_bnsc + 128, p_bnsh + 128, p_buf0);

    // 7. r2 conv + BN4 + ReLU -> buf1
    conv_gemm<64, 9, 64, 2><<<grid, 128>>>(
        p_buf0, p_wr2t, nullptr, nullptr, p_bnsc + 192, p_bnsh + 192, p_buf1);

    // 8. 1x1 conv + sigmoid -> d_out
    final_kernel<<<(sh::kPos + 255) / 256, 256>>>(
        p_buf1, out_w, out_b, (float*)d_out);
}